// round 3
// baseline (speedup 1.0000x reference)
#include <cuda_runtime.h>
#include <math.h>

#define Bq 16
#define Hq 512
#define Nq 64
#define Lq 2048

// ---------------- scratch (device globals: no allocation allowed) ----------
__device__ float g_y[Bq * Hq * Lq];                  // 64 MB activations
__device__ float g_wre[Hq * Nq], g_wim[Hq * Nq];
__device__ float g_cre[Hq * Nq], g_cim[Hq * Nq];

// ---------------- kernel 1: per-(h,n) discretized parameters ---------------
__global__ void param_kernel(const float* __restrict__ log_dt,
                             const float* __restrict__ A_re,
                             const float* __restrict__ A_im,
                             const float* __restrict__ C_re,
                             const float* __restrict__ C_im) {
    int i = blockIdx.x * blockDim.x + threadIdx.x;
    if (i >= Hq * Nq) return;
    int h = i / Nq;
    float dt  = expf(log_dt[h]);
    float ar  = -expf(A_re[i]);       // Re(A) < 0
    float ai  = A_im[i];
    float dre = dt * ar;
    float dim = dt * ai;
    float er  = expf(dre);
    float wre = er * cosf(dim);
    float wim = er * sinf(dim);
    // (w - 1) / A  via conjugate
    float den  = ar * ar + ai * ai;
    float numr = wre - 1.0f, numi = wim;
    float qre  = (numr * ar + numi * ai) / den;
    float qim  = (numi * ar - numr * ai) / den;
    float cr = C_re[i], ci = C_im[i];
    float ccre = cr * qre - ci * qim;
    float ccim = cr * qim + ci * qre;
    g_wre[i] = wre;
    g_wim[i] = wim;
    g_cre[i] = 2.0f * ccre;           // fold the 2*Re(.) factor in
    g_cim[i] = 2.0f * ccim;
}

// ---------------- kernel 2: diagonal SSM scan + skip + GELU ----------------
// 8 lanes per (b,h) sequence, 8 complex modes per lane.
#define MPL   8            // modes per lane
#define SEQS  16           // sequences per block (128 threads)
#define TCH   256          // time chunk staged through SMEM
#define SPITCH 260         // padded row pitch (floats) to dodge bank conflicts

__global__ __launch_bounds__(128) void scan_kernel(const float* __restrict__ u,
                                                   const float* __restrict__ D) {
    __shared__ float su[SEQS][SPITCH];
    __shared__ float sy[SEQS][SPITCH];

    int tid  = threadIdx.x;
    int grp  = tid >> 3;                 // 0..15  (sequence within block)
    int sub  = tid & 7;                  // 0..7   (lane within sequence)
    int gid0 = blockIdx.x * SEQS;        // first (b*H+h) of this block
    int gid  = gid0 + grp;
    int h    = gid & (Hq - 1);
    float Dh = D[h];

    float wre[MPL], wim[MPL], nwim[MPL], ccre[MPL], nccim[MPL];
    float xre[MPL], xim[MPL];
    int base = h * Nq + sub * MPL;
#pragma unroll
    for (int j = 0; j < MPL; j++) {
        wre[j]   = g_wre[base + j];
        wim[j]   = g_wim[base + j];
        nwim[j]  = -wim[j];
        ccre[j]  = g_cre[base + j];
        nccim[j] = -g_cim[base + j];
        xre[j] = 0.0f;
        xim[j] = 0.0f;
    }

    const float* ub = u   + (size_t)gid0 * Lq;
    float*       yb = g_y + (size_t)gid0 * Lq;

    for (int c0 = 0; c0 < Lq; c0 += TCH) {
        // cooperative float4 load: SEQS rows x TCH cols
#pragma unroll
        for (int it = 0; it < (SEQS * TCH / 4) / 128; it++) {
            int idx = tid + it * 128;
            int r   = idx >> 6;          // / (TCH/4)
            int c4  = idx & 63;
            float4 v = *(const float4*)(ub + (size_t)r * Lq + c0 + c4 * 4);
            *(float4*)&su[r][c4 * 4] = v;
        }
        __syncthreads();

        for (int t0 = 0; t0 < TCH; t0 += 8) {
            float hold = 0.0f;
#pragma unroll
            for (int k = 0; k < 8; k++) {
                float us = su[grp][t0 + k];
                float acc0 = 0.0f, acc1 = 0.0f;
#pragma unroll
                for (int j = 0; j < MPL; j++) {
                    float tr = fmaf(nwim[j], xim[j], us);
                    float nr = fmaf(wre[j],  xre[j], tr);
                    float ni = wim[j] * xre[j];
                    ni = fmaf(wre[j], xim[j], ni);
                    xre[j] = nr;
                    xim[j] = ni;
                    if (j & 1) {
                        acc1 = fmaf(ccre[j],  nr, acc1);
                        acc1 = fmaf(nccim[j], ni, acc1);
                    } else {
                        acc0 = fmaf(ccre[j],  nr, acc0);
                        acc0 = fmaf(nccim[j], ni, acc0);
                    }
                }
                float v = acc0 + acc1;
                v += __shfl_xor_sync(0xFFFFFFFFu, v, 1);
                v += __shfl_xor_sync(0xFFFFFFFFu, v, 2);
                v += __shfl_xor_sync(0xFFFFFFFFu, v, 4);
                float y = fmaf(Dh, us, v);
                if (k == sub) hold = y;       // each lane keeps one timestep
            }
            // exact (erf) GELU, one per lane per 8 steps
            float gel = 0.5f * hold * (1.0f + erff(hold * 0.70710678118654752f));
            sy[grp][t0 + sub] = gel;
        }
        __syncthreads();

        // cooperative float4 store of activations
#pragma unroll
        for (int it = 0; it < (SEQS * TCH / 4) / 128; it++) {
            int idx = tid + it * 128;
            int r   = idx >> 6;
            int c4  = idx & 63;
            *(float4*)(yb + (size_t)r * Lq + c0 + c4 * 4) = *(float4*)&sy[r][c4 * 4];
        }
        __syncthreads();
    }
}

// ---------------- kernel 3: out[b] = W (512x512) @ y_act[b] (512x2048) + bias
// Register-staged prefetch: next K-tile loaded into registers during compute.
#define BM 128
#define BN 128
#define BK 8
#define TM 8
#define TN 8

__global__ __launch_bounds__(256) void gemm_kernel(const float* __restrict__ W,
                                                   const float* __restrict__ bias,
                                                   float* __restrict__ out) {
    __shared__ float As[BK][BM];   // [k][v]
    __shared__ float Bs[BK][BN];   // [k][l]

    int b  = blockIdx.z;
    int v0 = blockIdx.y * BM;
    int l0 = blockIdx.x * BN;
    const float* Y = g_y + (size_t)b * Hq * Lq;

    int tid = threadIdx.x;
    int tx  = tid & 15;            // 0..15
    int ty  = tid >> 4;            // 0..15
    int row = ty * TM;             // within BM
    int col = tx * TN;             // within BN

    float acc[TM][TN];
#pragma unroll
    for (int i = 0; i < TM; i++)
#pragma unroll
        for (int j = 0; j < TN; j++) acc[i][j] = 0.0f;

    int av = tid >> 1;             // A row loaded by this thread (0..127)
    int ak = (tid & 1) * 4;        // A k-offset (0 or 4)
    int bk = tid >> 5;             // B k-row   (0..7)
    int bl = (tid & 31) * 4;       // B col     (0..124)

    // prologue: fetch tile 0 into registers
    float4 pa = *(const float4*)(W + (size_t)(v0 + av) * Hq + 0 + ak);
    float4 pb = *(const float4*)(Y + (size_t)(0 + bk) * Lq + l0 + bl);

    for (int k0 = 0; k0 < Hq; k0 += BK) {
        // commit prefetched tile to SMEM
        As[ak + 0][av] = pa.x;
        As[ak + 1][av] = pa.y;
        As[ak + 2][av] = pa.z;
        As[ak + 3][av] = pa.w;
        *(float4*)&Bs[bk][bl] = pb;
        __syncthreads();

        // issue next tile's global loads early (latency hidden by FMAs)
        int k1 = k0 + BK;
        if (k1 < Hq) {
            pa = *(const float4*)(W + (size_t)(v0 + av) * Hq + k1 + ak);
            pb = *(const float4*)(Y + (size_t)(k1 + bk) * Lq + l0 + bl);
        }

#pragma unroll
        for (int k = 0; k < BK; k++) {
            float ra[TM], rb[TN];
#pragma unroll
            for (int i = 0; i < TM; i += 4)
                *(float4*)&ra[i] = *(const float4*)&As[k][row + i];
#pragma unroll
            for (int j = 0; j < TN; j += 4)
                *(float4*)&rb[j] = *(const float4*)&Bs[k][col + j];
#pragma unroll
            for (int i = 0; i < TM; i++)
#pragma unroll
                for (int j = 0; j < TN; j++)
                    acc[i][j] = fmaf(ra[i], rb[j], acc[i][j]);
        }
        __syncthreads();
    }

    // epilogue: add bias, write out[b][v][l]
#pragma unroll
    for (int i = 0; i < TM; i++) {
        float bs = bias[v0 + row + i];
        float* op = out + (size_t)b * Hq * Lq + (size_t)(v0 + row + i) * Lq + l0 + col;
#pragma unroll
        for (int j = 0; j < TN; j += 4) {
            float4 v;
            v.x = acc[i][j + 0] + bs;
            v.y = acc[i][j + 1] + bs;
            v.z = acc[i][j + 2] + bs;
            v.w = acc[i][j + 3] + bs;
            *(float4*)(op + j) = v;
        }
    }
}

// ---------------- launch ----------------------------------------------------
extern "C" void kernel_launch(void* const* d_in, const int* in_sizes, int n_in,
                              void* d_out, int out_size) {
    (void)in_sizes; (void)n_in; (void)out_size;
    const float* u      = (const float*)d_in[0];
    const float* log_dt = (const float*)d_in[1];
    const float* A_re   = (const float*)d_in[2];
    const float* A_im   = (const float*)d_in[3];
    const float* C_re   = (const float*)d_in[4];
    const float* C_im   = (const float*)d_in[5];
    const float* D      = (const float*)d_in[6];
    const float* W      = (const float*)d_in[7];
    const float* bias   = (const float*)d_in[8];
    float* out = (float*)d_out;

    param_kernel<<<(Hq * Nq + 255) / 256, 256>>>(log_dt, A_re, A_im, C_re, C_im);
    scan_kernel<<<Bq * Hq / SEQS, 128>>>(u, D);
    dim3 g(Lq / BN, Hq / BM, Bq);
    gemm_kernel<<<g, 256>>>(W, bias, out);
}

// round 4
// speedup vs baseline: 1.2991x; 1.2991x over previous
#include <cuda_runtime.h>
#include <cuda_bf16.h>
#include <math.h>

#define Bq 16
#define Hq 512
#define Nq 64
#define Lq 2048

// ---------------- scratch (device globals: no allocation allowed) ----------
__device__ __nv_bfloat16 g_yh[Bq * Hq * Lq];         // activations hi (32 MB)
__device__ __nv_bfloat16 g_yl[Bq * Hq * Lq];         // activations lo (32 MB)
__device__ __nv_bfloat16 g_Wh[Hq * Hq], g_Wl[Hq * Hq];
__device__ float g_wre[Hq * Nq], g_wim[Hq * Nq];
__device__ float g_cre[Hq * Nq], g_cim[Hq * Nq];

// ---------------- f32x2 packed-math helpers --------------------------------
typedef unsigned long long u64;
__device__ __forceinline__ u64 pk2(float a, float b) {
    u64 r; asm("mov.b64 %0,{%1,%2};" : "=l"(r) : "f"(a), "f"(b)); return r;
}
__device__ __forceinline__ float2 upk2(u64 v) {
    float2 f; asm("mov.b64 {%0,%1},%2;" : "=f"(f.x), "=f"(f.y) : "l"(v)); return f;
}
__device__ __forceinline__ u64 ffma2(u64 a, u64 b, u64 c) {
    u64 d; asm("fma.rn.f32x2 %0,%1,%2,%3;" : "=l"(d) : "l"(a), "l"(b), "l"(c)); return d;
}
__device__ __forceinline__ u64 fmul2(u64 a, u64 b) {
    u64 d; asm("mul.rn.f32x2 %0,%1,%2;" : "=l"(d) : "l"(a), "l"(b)); return d;
}

// ---------------- kernel 1: params + W hi/lo split (fused) -----------------
__global__ void prep_kernel(const float* __restrict__ log_dt,
                            const float* __restrict__ A_re,
                            const float* __restrict__ A_im,
                            const float* __restrict__ C_re,
                            const float* __restrict__ C_im,
                            const float* __restrict__ W) {
    int i = blockIdx.x * blockDim.x + threadIdx.x;
    if (i < Hq * Hq) {
        float w = W[i];
        __nv_bfloat16 h = __float2bfloat16(w);
        g_Wh[i] = h;
        g_Wl[i] = __float2bfloat16(w - __bfloat162float(h));
    }
    if (i < Hq * Nq) {
        int h = i / Nq;
        float dt  = expf(log_dt[h]);
        float ar  = -expf(A_re[i]);       // Re(A) < 0
        float ai  = A_im[i];
        float er  = expf(dt * ar);
        float wre = er * cosf(dt * ai);
        float wim = er * sinf(dt * ai);
        float den  = ar * ar + ai * ai;   // (w-1)/A via conjugate
        float numr = wre - 1.0f, numi = wim;
        float qre  = (numr * ar + numi * ai) / den;
        float qim  = (numi * ar - numr * ai) / den;
        float cr = C_re[i], ci = C_im[i];
        g_wre[i] = wre;
        g_wim[i] = wim;
        g_cre[i] = 2.0f * (cr * qre - ci * qim);
        g_cim[i] = 2.0f * (cr * qim + ci * qre);
    }
}

// ---------------- kernel 2: diagonal SSM scan (f32x2) + skip + GELU --------
#define MPL   8            // modes per lane (4 f32x2 pairs)
#define SEQS  16           // sequences per block (128 threads)
#define TCH   256          // time chunk staged through SMEM
#define SPITCH 260

__global__ __launch_bounds__(128) void scan_kernel(const float* __restrict__ u,
                                                   const float* __restrict__ D) {
    __shared__ float su[SEQS][SPITCH];
    __shared__ float sy[SEQS][SPITCH];

    int tid  = threadIdx.x;
    int grp  = tid >> 3;                 // sequence within block
    int sub  = tid & 7;                  // lane within sequence
    int gid0 = blockIdx.x * SEQS;
    int gid  = gid0 + grp;
    int h    = gid & (Hq - 1);
    float Dh = D[h];

    u64 wre2[4], nwim2[4], wim2[4], ccre2[4], nccim2[4], xre2[4], xim2[4];
    int base = h * Nq + sub * MPL;
#pragma unroll
    for (int p = 0; p < 4; p++) {
        float2 wr = *(const float2*)&g_wre[base + 2 * p];
        float2 wi = *(const float2*)&g_wim[base + 2 * p];
        float2 cr = *(const float2*)&g_cre[base + 2 * p];
        float2 ci = *(const float2*)&g_cim[base + 2 * p];
        wre2[p]   = pk2(wr.x, wr.y);
        wim2[p]   = pk2(wi.x, wi.y);
        nwim2[p]  = pk2(-wi.x, -wi.y);
        ccre2[p]  = pk2(cr.x, cr.y);
        nccim2[p] = pk2(-ci.x, -ci.y);
        xre2[p] = 0ull;
        xim2[p] = 0ull;
    }

    const float* ub = u + (size_t)gid0 * Lq;

    for (int c0 = 0; c0 < Lq; c0 += TCH) {
#pragma unroll
        for (int it = 0; it < (SEQS * TCH / 4) / 128; it++) {
            int idx = tid + it * 128;
            int r   = idx >> 6;
            int c4  = idx & 63;
            float4 v = *(const float4*)(ub + (size_t)r * Lq + c0 + c4 * 4);
            *(float4*)&su[r][c4 * 4] = v;
        }
        __syncthreads();

        for (int t0 = 0; t0 < TCH; t0 += 8) {
            float hold = 0.0f;
#pragma unroll
            for (int k = 0; k < 8; k++) {
                float us = su[grp][t0 + k];
                u64 u2   = pk2(us, us);
                u64 acc2 = 0ull;
#pragma unroll
                for (int p = 0; p < 4; p++) {
                    u64 t  = ffma2(nwim2[p], xim2[p], u2);
                    u64 nr = ffma2(wre2[p],  xre2[p], t);
                    u64 ni = fmul2(wim2[p],  xre2[p]);
                    ni     = ffma2(wre2[p],  xim2[p], ni);
                    xre2[p] = nr;
                    xim2[p] = ni;
                    acc2 = ffma2(ccre2[p],  nr, acc2);
                    acc2 = ffma2(nccim2[p], ni, acc2);
                }
                float2 ab = upk2(acc2);
                float v = ab.x + ab.y;
                v += __shfl_xor_sync(0xFFFFFFFFu, v, 1);
                v += __shfl_xor_sync(0xFFFFFFFFu, v, 2);
                v += __shfl_xor_sync(0xFFFFFFFFu, v, 4);
                float y = fmaf(Dh, us, v);
                if (k == sub) hold = y;
            }
            float gel = 0.5f * hold * (1.0f + erff(hold * 0.70710678118654752f));
            sy[grp][t0 + sub] = gel;
        }
        __syncthreads();

        // store activations as bf16 hi/lo pairs
#pragma unroll
        for (int it = 0; it < (SEQS * TCH / 4) / 128; it++) {
            int idx = tid + it * 128;
            int r   = idx >> 6;
            int c4  = idx & 63;
            float4 v = *(float4*)&sy[r][c4 * 4];
            __nv_bfloat16 h0 = __float2bfloat16(v.x);
            __nv_bfloat16 h1 = __float2bfloat16(v.y);
            __nv_bfloat16 h2 = __float2bfloat16(v.z);
            __nv_bfloat16 h3 = __float2bfloat16(v.w);
            __nv_bfloat16 l0b = __float2bfloat16(v.x - __bfloat162float(h0));
            __nv_bfloat16 l1b = __float2bfloat16(v.y - __bfloat162float(h1));
            __nv_bfloat16 l2b = __float2bfloat16(v.z - __bfloat162float(h2));
            __nv_bfloat16 l3b = __float2bfloat16(v.w - __bfloat162float(h3));
            uint2 ph, pl;
            ph.x = ((unsigned)__bfloat16_as_ushort(h1) << 16) | __bfloat16_as_ushort(h0);
            ph.y = ((unsigned)__bfloat16_as_ushort(h3) << 16) | __bfloat16_as_ushort(h2);
            pl.x = ((unsigned)__bfloat16_as_ushort(l1b) << 16) | __bfloat16_as_ushort(l0b);
            pl.y = ((unsigned)__bfloat16_as_ushort(l3b) << 16) | __bfloat16_as_ushort(l2b);
            size_t off = (size_t)(gid0 + r) * Lq + c0 + c4 * 4;
            *(uint2*)(g_yh + off) = ph;
            *(uint2*)(g_yl + off) = pl;
        }
        __syncthreads();
    }
}

// ---------------- kernel 3: bf16-split tensor-core GEMM --------------------
// out[b] (512 x 2048) = W (512x512) @ Y[b] (512x2048) + bias
// 3-term split: Wh*Yh + Wl*Yh + Wh*Yl  (fp32 accumulate)
#define GBM 128
#define GBN 128
#define GBK 32
#define ASTR 40    // As row stride (elems): 80B -> conflict-free ldmatrix
#define BSTR 136   // Bs row stride (elems): 272B -> conflict-free ldmatrix

#define LDSM4(r0, r1, r2, r3, addr) \
    asm volatile("ldmatrix.sync.aligned.m8n8.x4.shared.b16 {%0,%1,%2,%3},[%4];" \
                 : "=r"(r0), "=r"(r1), "=r"(r2), "=r"(r3) : "r"(addr))
#define LDSM4T(r0, r1, r2, r3, addr) \
    asm volatile("ldmatrix.sync.aligned.m8n8.x4.trans.shared.b16 {%0,%1,%2,%3},[%4];" \
                 : "=r"(r0), "=r"(r1), "=r"(r2), "=r"(r3) : "r"(addr))
#define MMA16816(d, a, b0, b1) \
    asm volatile("mma.sync.aligned.m16n8k16.row.col.f32.bf16.bf16.f32 " \
                 "{%0,%1,%2,%3},{%4,%5,%6,%7},{%8,%9},{%0,%1,%2,%3};" \
                 : "+f"(d[0]), "+f"(d[1]), "+f"(d[2]), "+f"(d[3]) \
                 : "r"(a[0]), "r"(a[1]), "r"(a[2]), "r"(a[3]), "r"(b0), "r"(b1))
#define CPA16(dst, src) \
    asm volatile("cp.async.cg.shared.global [%0],[%1],16;" :: "r"(dst), "l"(src))

__global__ __launch_bounds__(256) void gemm_kernel(const float* __restrict__ bias,
                                                   float* __restrict__ out) {
    __shared__ __align__(16) __nv_bfloat16 As[2][GBM * ASTR];  // [ver][m*ASTR+k]
    __shared__ __align__(16) __nv_bfloat16 Bs[2][GBK * BSTR];  // [ver][k*BSTR+n]

    int b   = blockIdx.z;
    int v0  = blockIdx.y * GBM;
    int l0  = blockIdx.x * GBN;
    int tid = threadIdx.x;
    int lane = tid & 31;
    int wid  = tid >> 5;
    int wm = wid >> 1;            // 0..3 -> m offset wm*32
    int wn = wid & 1;             // 0..1 -> n offset wn*64

    float acc[2][8][4];
#pragma unroll
    for (int i = 0; i < 2; i++)
#pragma unroll
        for (int j = 0; j < 8; j++)
#pragma unroll
            for (int k = 0; k < 4; k++) acc[i][j][k] = 0.0f;

    unsigned as0 = (unsigned)__cvta_generic_to_shared(&As[0][0]);
    unsigned as1 = (unsigned)__cvta_generic_to_shared(&As[1][0]);
    unsigned bs0 = (unsigned)__cvta_generic_to_shared(&Bs[0][0]);
    unsigned bs1 = (unsigned)__cvta_generic_to_shared(&Bs[1][0]);

    for (int k0 = 0; k0 < Hq; k0 += GBK) {
        // ---- async loads of this k-tile ----
#pragma unroll
        for (int q = 0; q < 2; q++) {
            int idx = tid + q * 256;
            int r = idx >> 2, c = (idx & 3) * 8;               // W: 128 rows x 32
            const __nv_bfloat16* swh = g_Wh + (size_t)(v0 + r) * Hq + k0 + c;
            const __nv_bfloat16* swl = g_Wl + (size_t)(v0 + r) * Hq + k0 + c;
            unsigned d = (r * ASTR + c) * 2;
            CPA16(as0 + d, swh);
            CPA16(as1 + d, swl);
        }
#pragma unroll
        for (int q = 0; q < 2; q++) {
            int idx = tid + q * 256;
            int r = idx >> 4, c = (idx & 15) * 8;              // Y: 32 rows x 128
            size_t off = (size_t)(b * Hq + k0 + r) * Lq + l0 + c;
            unsigned d = (r * BSTR + c) * 2;
            CPA16(bs0 + d, g_yh + off);
            CPA16(bs1 + d, g_yl + off);
        }
        asm volatile("cp.async.commit_group;");
        asm volatile("cp.async.wait_group 0;");
        __syncthreads();

        // ---- compute: 2 k16 steps ----
#pragma unroll
        for (int ks = 0; ks < 2; ks++) {
            unsigned ah[2][4], al[2][4], bh[4][4], bl[4][4];
#pragma unroll
            for (int mf = 0; mf < 2; mf++) {
                unsigned d = ((wm * 32 + mf * 16 + (lane & 15)) * ASTR
                              + ks * 16 + (lane >> 4) * 8) * 2;
                LDSM4(ah[mf][0], ah[mf][1], ah[mf][2], ah[mf][3], as0 + d);
                LDSM4(al[mf][0], al[mf][1], al[mf][2], al[mf][3], as1 + d);
            }
#pragma unroll
            for (int j = 0; j < 4; j++) {
                unsigned d = ((ks * 16 + (lane & 15)) * BSTR
                              + wn * 64 + j * 16 + (lane >> 4) * 8) * 2;
                LDSM4T(bh[j][0], bh[j][1], bh[j][2], bh[j][3], bs0 + d);
                LDSM4T(bl[j][0], bl[j][1], bl[j][2], bl[j][3], bs1 + d);
            }
#pragma unroll
            for (int mf = 0; mf < 2; mf++)
#pragma unroll
                for (int n8 = 0; n8 < 8; n8++) {
                    int j = n8 >> 1, hi = (n8 & 1) * 2;
                    MMA16816(acc[mf][n8], ah[mf], bh[j][hi], bh[j][hi + 1]);
                    MMA16816(acc[mf][n8], al[mf], bh[j][hi], bh[j][hi + 1]);
                    MMA16816(acc[mf][n8], ah[mf], bl[j][hi], bl[j][hi + 1]);
                }
        }
        __syncthreads();
    }

    // ---- epilogue: bias + store ----
    int tq = lane >> 2, tr = lane & 3;
#pragma unroll
    for (int mf = 0; mf < 2; mf++) {
        int v = v0 + wm * 32 + mf * 16 + tq;
        float bv0 = bias[v], bv1 = bias[v + 8];
#pragma unroll
        for (int n8 = 0; n8 < 8; n8++) {
            int l = l0 + wn * 64 + n8 * 8 + tr * 2;
            float2 s0, s1;
            s0.x = acc[mf][n8][0] + bv0; s0.y = acc[mf][n8][1] + bv0;
            s1.x = acc[mf][n8][2] + bv1; s1.y = acc[mf][n8][3] + bv1;
            *(float2*)(out + ((size_t)b * Hq + v) * Lq + l)     = s0;
            *(float2*)(out + ((size_t)b * Hq + v + 8) * Lq + l) = s1;
        }
    }
}

// ---------------- launch ----------------------------------------------------
extern "C" void kernel_launch(void* const* d_in, const int* in_sizes, int n_in,
                              void* d_out, int out_size) {
    (void)in_sizes; (void)n_in; (void)out_size;
    const float* u      = (const float*)d_in[0];
    const float* log_dt = (const float*)d_in[1];
    const float* A_re   = (const float*)d_in[2];
    const float* A_im   = (const float*)d_in[3];
    const float* C_re   = (const float*)d_in[4];
    const float* C_im   = (const float*)d_in[5];
    const float* D      = (const float*)d_in[6];
    const float* W      = (const float*)d_in[7];
    const float* bias   = (const float*)d_in[8];
    float* out = (float*)d_out;

    prep_kernel<<<(Hq * Hq + 255) / 256, 256>>>(log_dt, A_re, A_im, C_re, C_im, W);
    scan_kernel<<<Bq * Hq / SEQS, 128>>>(u, D);
    dim3 g(Lq / GBN, Hq / GBM, Bq);
    gemm_kernel<<<g, 256>>>(bias, out);
}

// round 6
// speedup vs baseline: 1.4810x; 1.1400x over previous
#include <cuda_runtime.h>
#include <cuda_bf16.h>
#include <math.h>

#define Bq 16
#define Hq 512
#define Nq 64
#define Lq 2048

// ---------------- scratch (device globals: no allocation allowed) ----------
__device__ __nv_bfloat16 g_yh[Bq * Hq * Lq];         // activations hi (32 MB)
__device__ __nv_bfloat16 g_yl[Bq * Hq * Lq];         // activations lo (32 MB)
__device__ __nv_bfloat16 g_Wh[Hq * Hq], g_Wl[Hq * Hq];
__device__ float g_wre[Hq * Nq], g_wim[Hq * Nq];
__device__ float g_cre[Hq * Nq], g_cim[Hq * Nq];

// ---------------- f32x2 packed-math helpers --------------------------------
typedef unsigned long long u64;
__device__ __forceinline__ u64 pk2(float a, float b) {
    u64 r; asm("mov.b64 %0,{%1,%2};" : "=l"(r) : "f"(a), "f"(b)); return r;
}
__device__ __forceinline__ float2 upk2(u64 v) {
    float2 f; asm("mov.b64 {%0,%1},%2;" : "=f"(f.x), "=f"(f.y) : "l"(v)); return f;
}
__device__ __forceinline__ u64 ffma2(u64 a, u64 b, u64 c) {
    u64 d; asm("fma.rn.f32x2 %0,%1,%2,%3;" : "=l"(d) : "l"(a), "l"(b), "l"(c)); return d;
}
__device__ __forceinline__ u64 fmul2(u64 a, u64 b) {
    u64 d; asm("mul.rn.f32x2 %0,%1,%2;" : "=l"(d) : "l"(a), "l"(b)); return d;
}

// ---------------- kernel 1: params + W hi/lo split (fused) -----------------
__global__ void prep_kernel(const float* __restrict__ log_dt,
                            const float* __restrict__ A_re,
                            const float* __restrict__ A_im,
                            const float* __restrict__ C_re,
                            const float* __restrict__ C_im,
                            const float* __restrict__ W) {
    int i = blockIdx.x * blockDim.x + threadIdx.x;
    if (i < Hq * Hq) {
        float w = W[i];
        __nv_bfloat16 h = __float2bfloat16(w);
        g_Wh[i] = h;
        g_Wl[i] = __float2bfloat16(w - __bfloat162float(h));
    }
    if (i < Hq * Nq) {
        int h = i / Nq;
        float dt  = expf(log_dt[h]);
        float ar  = -expf(A_re[i]);       // Re(A) < 0
        float ai  = A_im[i];
        float er  = expf(dt * ar);
        float wre = er * cosf(dt * ai);
        float wim = er * sinf(dt * ai);
        float den  = ar * ar + ai * ai;   // (w-1)/A via conjugate
        float numr = wre - 1.0f, numi = wim;
        float qre  = (numr * ar + numi * ai) / den;
        float qim  = (numi * ar - numr * ai) / den;
        float cr = C_re[i], ci = C_im[i];
        g_wre[i] = wre;
        g_wim[i] = wim;
        g_cre[i] = 2.0f * (cr * qre - ci * qim);
        g_cim[i] = 2.0f * (cr * qim + ci * qre);
    }
}

// ---------------- kernel 2: diagonal SSM scan (f32x2) + skip + GELU --------
#define MPL   8
#define SEQS  16
#define TCH   256
#define SPITCH 260

__global__ __launch_bounds__(128) void scan_kernel(const float* __restrict__ u,
                                                   const float* __restrict__ D) {
    __shared__ float su[SEQS][SPITCH];
    __shared__ float sy[SEQS][SPITCH];

    int tid  = threadIdx.x;
    int grp  = tid >> 3;
    int sub  = tid & 7;
    int gid0 = blockIdx.x * SEQS;
    int gid  = gid0 + grp;
    int h    = gid & (Hq - 1);
    float Dh = D[h];

    u64 wre2[4], nwim2[4], wim2[4], ccre2[4], nccim2[4], xre2[4], xim2[4];
    int base = h * Nq + sub * MPL;
#pragma unroll
    for (int p = 0; p < 4; p++) {
        float2 wr = *(const float2*)&g_wre[base + 2 * p];
        float2 wi = *(const float2*)&g_wim[base + 2 * p];
        float2 cr = *(const float2*)&g_cre[base + 2 * p];
        float2 ci = *(const float2*)&g_cim[base + 2 * p];
        wre2[p]   = pk2(wr.x, wr.y);
        wim2[p]   = pk2(wi.x, wi.y);
        nwim2[p]  = pk2(-wi.x, -wi.y);
        ccre2[p]  = pk2(cr.x, cr.y);
        nccim2[p] = pk2(-ci.x, -ci.y);
        xre2[p] = 0ull;
        xim2[p] = 0ull;
    }

    const float* ub = u + (size_t)gid0 * Lq;

    for (int c0 = 0; c0 < Lq; c0 += TCH) {
#pragma unroll
        for (int it = 0; it < (SEQS * TCH / 4) / 128; it++) {
            int idx = tid + it * 128;
            int r   = idx >> 6;
            int c4  = idx & 63;
            float4 v = *(const float4*)(ub + (size_t)r * Lq + c0 + c4 * 4);
            *(float4*)&su[r][c4 * 4] = v;
        }
        __syncthreads();

        for (int t0 = 0; t0 < TCH; t0 += 8) {
            float hold = 0.0f;
#pragma unroll
            for (int k = 0; k < 8; k++) {
                float us = su[grp][t0 + k];
                u64 u2   = pk2(us, us);
                u64 acc2 = 0ull;
#pragma unroll
                for (int p = 0; p < 4; p++) {
                    u64 t  = ffma2(nwim2[p], xim2[p], u2);
                    u64 nr = ffma2(wre2[p],  xre2[p], t);
                    u64 ni = fmul2(wim2[p],  xre2[p]);
                    ni     = ffma2(wre2[p],  xim2[p], ni);
                    xre2[p] = nr;
                    xim2[p] = ni;
                    acc2 = ffma2(ccre2[p],  nr, acc2);
                    acc2 = ffma2(nccim2[p], ni, acc2);
                }
                float2 ab = upk2(acc2);
                float v = ab.x + ab.y;
                v += __shfl_xor_sync(0xFFFFFFFFu, v, 1);
                v += __shfl_xor_sync(0xFFFFFFFFu, v, 2);
                v += __shfl_xor_sync(0xFFFFFFFFu, v, 4);
                float y = fmaf(Dh, us, v);
                if (k == sub) hold = y;
            }
            float gel = 0.5f * hold * (1.0f + erff(hold * 0.70710678118654752f));
            sy[grp][t0 + sub] = gel;
        }
        __syncthreads();

#pragma unroll
        for (int it = 0; it < (SEQS * TCH / 4) / 128; it++) {
            int idx = tid + it * 128;
            int r   = idx >> 6;
            int c4  = idx & 63;
            float4 v = *(float4*)&sy[r][c4 * 4];
            __nv_bfloat16 h0 = __float2bfloat16(v.x);
            __nv_bfloat16 h1 = __float2bfloat16(v.y);
            __nv_bfloat16 h2 = __float2bfloat16(v.z);
            __nv_bfloat16 h3 = __float2bfloat16(v.w);
            __nv_bfloat16 l0b = __float2bfloat16(v.x - __bfloat162float(h0));
            __nv_bfloat16 l1b = __float2bfloat16(v.y - __bfloat162float(h1));
            __nv_bfloat16 l2b = __float2bfloat16(v.z - __bfloat162float(h2));
            __nv_bfloat16 l3b = __float2bfloat16(v.w - __bfloat162float(h3));
            uint2 ph, pl;
            ph.x = ((unsigned)__bfloat16_as_ushort(h1) << 16) | __bfloat16_as_ushort(h0);
            ph.y = ((unsigned)__bfloat16_as_ushort(h3) << 16) | __bfloat16_as_ushort(h2);
            pl.x = ((unsigned)__bfloat16_as_ushort(l1b) << 16) | __bfloat16_as_ushort(l0b);
            pl.y = ((unsigned)__bfloat16_as_ushort(l3b) << 16) | __bfloat16_as_ushort(l2b);
            size_t off = (size_t)(gid0 + r) * Lq + c0 + c4 * 4;
            *(uint2*)(g_yh + off) = ph;
            *(uint2*)(g_yl + off) = pl;
        }
        __syncthreads();
    }
}

// ---------------- kernel 3: bf16-split tensor-core GEMM, 2-stage pipeline --
// out[b] (512 x 2048) = W (512x512) @ Y[b] (512x2048) + bias
// 3-term split: Wh*Yh + Wl*Yh + Wh*Yl  (fp32 accumulate)
#define GBM 128
#define GBN 128
#define GBK 32
#define ASTR 40    // As row stride (elems)
#define BSTR 136   // Bs row stride (elems)
#define A_ELEMS (GBM * ASTR)
#define B_ELEMS (GBK * BSTR)
// dynamic smem layout (byte offsets): [stage][hi/lo]
#define AOFF(st, hl) (((st) * 2 + (hl)) * A_ELEMS * 2)
#define BOFF(st, hl) (4 * A_ELEMS * 2 + ((st) * 2 + (hl)) * B_ELEMS * 2)
#define SMEM_GEMM (4 * A_ELEMS * 2 + 4 * B_ELEMS * 2)

#define LDSM4(r0, r1, r2, r3, addr) \
    asm volatile("ldmatrix.sync.aligned.m8n8.x4.shared.b16 {%0,%1,%2,%3},[%4];" \
                 : "=r"(r0), "=r"(r1), "=r"(r2), "=r"(r3) : "r"(addr))
#define LDSM4T(r0, r1, r2, r3, addr) \
    asm volatile("ldmatrix.sync.aligned.m8n8.x4.trans.shared.b16 {%0,%1,%2,%3},[%4];" \
                 : "=r"(r0), "=r"(r1), "=r"(r2), "=r"(r3) : "r"(addr))
#define MMA16816(d, a, b0, b1) \
    asm volatile("mma.sync.aligned.m16n8k16.row.col.f32.bf16.bf16.f32 " \
                 "{%0,%1,%2,%3},{%4,%5,%6,%7},{%8,%9},{%0,%1,%2,%3};" \
                 : "+f"(d[0]), "+f"(d[1]), "+f"(d[2]), "+f"(d[3]) \
                 : "r"(a[0]), "r"(a[1]), "r"(a[2]), "r"(a[3]), "r"(b0), "r"(b1))
#define CPA16(dst, src) \
    asm volatile("cp.async.cg.shared.global [%0],[%1],16;" :: "r"(dst), "l"(src))

extern __shared__ char dsm[];

__device__ __forceinline__ unsigned smem_u32g(const void* p) {
    unsigned a;
    asm("{ .reg .u64 t; cvta.to.shared.u64 t, %1; cvt.u32.u64 %0, t; }"
        : "=r"(a) : "l"(p));
    return a;
}

__global__ __launch_bounds__(256) void gemm_kernel(const float* __restrict__ bias,
                                                   float* __restrict__ out) {
    unsigned sb = smem_u32g(dsm);
    int b   = blockIdx.z;
    int v0  = blockIdx.y * GBM;
    int l0  = blockIdx.x * GBN;
    int tid = threadIdx.x;
    int lane = tid & 31;
    int wid  = tid >> 5;
    int wm = wid >> 1;            // 0..3 -> m offset wm*32
    int wn = wid & 1;             // 0..1 -> n offset wn*64

    float acc[2][8][4];
#pragma unroll
    for (int i = 0; i < 2; i++)
#pragma unroll
        for (int j = 0; j < 8; j++)
#pragma unroll
            for (int k = 0; k < 4; k++) acc[i][j][k] = 0.0f;

    // per-thread load coordinates
    int ar_ = tid >> 2, ac_ = (tid & 3) * 8;       // +q*256: rows 0..127 over 2 iters? no:
    // A tile: 128 rows x 32 cols, 8 elems per cp => 512 cps, 2 per thread
    // B tile: 32 rows x 128 cols => 512 cps, 2 per thread

#define LOAD_TILE(k0, st) do {                                              \
    _Pragma("unroll")                                                       \
    for (int q = 0; q < 2; q++) {                                           \
        int idx = tid + q * 256;                                            \
        int r = idx >> 2, c = (idx & 3) * 8;                                \
        size_t src = (size_t)(v0 + r) * Hq + (k0) + c;                      \
        unsigned d = (unsigned)(r * ASTR + c) * 2;                          \
        CPA16(sb + AOFF(st, 0) + d, g_Wh + src);                            \
        CPA16(sb + AOFF(st, 1) + d, g_Wl + src);                            \
    }                                                                       \
    _Pragma("unroll")                                                       \
    for (int q = 0; q < 2; q++) {                                           \
        int idx = tid + q * 256;                                            \
        int r = idx >> 4, c = (idx & 15) * 8;                               \
        size_t src = (size_t)(b * Hq + (k0) + r) * Lq + l0 + c;             \
        unsigned d = (unsigned)(r * BSTR + c) * 2;                          \
        CPA16(sb + BOFF(st, 0) + d, g_yh + src);                            \
        CPA16(sb + BOFF(st, 1) + d, g_yl + src);                            \
    }                                                                       \
} while (0)

    // prologue: stage tiles 0 and 1
    LOAD_TILE(0, 0);
    asm volatile("cp.async.commit_group;");
    LOAD_TILE(GBK, 1);
    asm volatile("cp.async.commit_group;");

    for (int ch = 0; ch < Hq / GBK; ch++) {
        int st = ch & 1;
        asm volatile("cp.async.wait_group 1;");
        __syncthreads();

        unsigned ah_base = sb + AOFF(st, 0);
        unsigned al_base = sb + AOFF(st, 1);
        unsigned bh_base = sb + BOFF(st, 0);
        unsigned bl_base = sb + BOFF(st, 1);

#pragma unroll
        for (int ks = 0; ks < 2; ks++) {
            unsigned ah[2][4], al[2][4], bh[4][4], bl[4][4];
#pragma unroll
            for (int mf = 0; mf < 2; mf++) {
                unsigned d = ((wm * 32 + mf * 16 + (lane & 15)) * ASTR
                              + ks * 16 + (lane >> 4) * 8) * 2;
                LDSM4(ah[mf][0], ah[mf][1], ah[mf][2], ah[mf][3], ah_base + d);
                LDSM4(al[mf][0], al[mf][1], al[mf][2], al[mf][3], al_base + d);
            }
#pragma unroll
            for (int j = 0; j < 4; j++) {
                unsigned d = ((ks * 16 + (lane & 15)) * BSTR
                              + wn * 64 + j * 16 + (lane >> 4) * 8) * 2;
                LDSM4T(bh[j][0], bh[j][1], bh[j][2], bh[j][3], bh_base + d);
                LDSM4T(bl[j][0], bl[j][1], bl[j][2], bl[j][3], bl_base + d);
            }
#pragma unroll
            for (int mf = 0; mf < 2; mf++)
#pragma unroll
                for (int n8 = 0; n8 < 8; n8++) {
                    int j = n8 >> 1, hi = (n8 & 1) * 2;
                    MMA16816(acc[mf][n8], ah[mf], bh[j][hi], bh[j][hi + 1]);
                    MMA16816(acc[mf][n8], al[mf], bh[j][hi], bh[j][hi + 1]);
                    MMA16816(acc[mf][n8], ah[mf], bl[j][hi], bl[j][hi + 1]);
                }
        }
        __syncthreads();

        int knext = (ch + 2) * GBK;
        if (knext < Hq) {
            LOAD_TILE(knext, st);
        }
        asm volatile("cp.async.commit_group;");
    }

    // ---- epilogue: bias + store ----
    int tq = lane >> 2, tr = lane & 3;
#pragma unroll
    for (int mf = 0; mf < 2; mf++) {
        int v = v0 + wm * 32 + mf * 16 + tq;
        float bv0 = bias[v], bv1 = bias[v + 8];
#pragma unroll
        for (int n8 = 0; n8 < 8; n8++) {
            int l = l0 + wn * 64 + n8 * 8 + tr * 2;
            float2 s0, s1;
            s0.x = acc[mf][n8][0] + bv0; s0.y = acc[mf][n8][1] + bv0;
            s1.x = acc[mf][n8][2] + bv1; s1.y = acc[mf][n8][3] + bv1;
            *(float2*)(out + ((size_t)b * Hq + v) * Lq + l)     = s0;
            *(float2*)(out + ((size_t)b * Hq + v + 8) * Lq + l) = s1;
        }
    }
}

// ---------------- launch ----------------------------------------------------
extern "C" void kernel_launch(void* const* d_in, const int* in_sizes, int n_in,
                              void* d_out, int out_size) {
    (void)in_sizes; (void)n_in; (void)out_size;
    const float* u      = (const float*)d_in[0];
    const float* log_dt = (const float*)d_in[1];
    const float* A_re   = (const float*)d_in[2];
    const float* A_im   = (const float*)d_in[3];
    const float* C_re   = (const float*)d_in[4];
    const float* C_im   = (const float*)d_in[5];
    const float* D      = (const float*)d_in[6];
    const float* W      = (const float*)d_in[7];
    const float* bias   = (const float*)d_in[8];
    float* out = (float*)d_out;

    static int smem_set = 0;
    if (!smem_set) {
        cudaFuncSetAttribute(gemm_kernel,
                             cudaFuncAttributeMaxDynamicSharedMemorySize,
                             SMEM_GEMM);
        smem_set = 1;
    }

    prep_kernel<<<(Hq * Hq + 255) / 256, 256>>>(log_dt, A_re, A_im, C_re, C_im, W);
    scan_kernel<<<Bq * Hq / SEQS, 128>>>(u, D);
    dim3 g(Lq / GBN, Hq / GBM, Bq);
    gemm_kernel<<<g, 256, SMEM_GEMM>>>(bias, out);
}

// round 7
// speedup vs baseline: 1.4944x; 1.0090x over previous
#include <cuda_runtime.h>
#include <cuda_bf16.h>
#include <math.h>

#define Bq 16
#define Hq 512
#define Nq 64
#define Lq 2048

// ---------------- scratch (device globals: no allocation allowed) ----------
__device__ __nv_bfloat16 g_yh[Bq * Hq * Lq];         // activations hi (32 MB)
__device__ __nv_bfloat16 g_yl[Bq * Hq * Lq];         // activations lo (32 MB)
__device__ __nv_bfloat16 g_Wh[Hq * Hq], g_Wl[Hq * Hq];
__device__ float g_wre[Hq * Nq], g_wim[Hq * Nq];
__device__ float g_cre[Hq * Nq], g_cim[Hq * Nq];

// ---------------- f32x2 packed-math helpers --------------------------------
typedef unsigned long long u64;
__device__ __forceinline__ u64 pk2(float a, float b) {
    u64 r; asm("mov.b64 %0,{%1,%2};" : "=l"(r) : "f"(a), "f"(b)); return r;
}
__device__ __forceinline__ float2 upk2(u64 v) {
    float2 f; asm("mov.b64 {%0,%1},%2;" : "=f"(f.x), "=f"(f.y) : "l"(v)); return f;
}
__device__ __forceinline__ u64 ffma2(u64 a, u64 b, u64 c) {
    u64 d; asm("fma.rn.f32x2 %0,%1,%2,%3;" : "=l"(d) : "l"(a), "l"(b), "l"(c)); return d;
}
__device__ __forceinline__ u64 fmul2(u64 a, u64 b) {
    u64 d; asm("mul.rn.f32x2 %0,%1,%2;" : "=l"(d) : "l"(a), "l"(b)); return d;
}

// ---------------- kernel 1: params + W hi/lo split (fused) -----------------
__global__ void prep_kernel(const float* __restrict__ log_dt,
                            const float* __restrict__ A_re,
                            const float* __restrict__ A_im,
                            const float* __restrict__ C_re,
                            const float* __restrict__ C_im,
                            const float* __restrict__ W) {
    int i = blockIdx.x * blockDim.x + threadIdx.x;
    if (i < Hq * Hq) {
        float w = W[i];
        __nv_bfloat16 h = __float2bfloat16(w);
        g_Wh[i] = h;
        g_Wl[i] = __float2bfloat16(w - __bfloat162float(h));
    }
    if (i < Hq * Nq) {
        int h = i / Nq;
        float dt  = expf(log_dt[h]);
        float ar  = -expf(A_re[i]);       // Re(A) < 0
        float ai  = A_im[i];
        float er  = expf(dt * ar);
        float wre = er * cosf(dt * ai);
        float wim = er * sinf(dt * ai);
        float den  = ar * ar + ai * ai;   // (w-1)/A via conjugate
        float numr = wre - 1.0f, numi = wim;
        float qre  = (numr * ar + numi * ai) / den;
        float qim  = (numi * ar - numr * ai) / den;
        float cr = C_re[i], ci = C_im[i];
        g_wre[i] = wre;
        g_wim[i] = wim;
        g_cre[i] = 2.0f * (cr * qre - ci * qim);
        g_cim[i] = 2.0f * (cr * qim + ci * qre);
    }
}

// ---------------- kernel 2: diagonal SSM scan (f32x2) + skip + GELU --------
#define MPL   8
#define SEQS  16
#define TCH   256
#define SPITCH 260

__global__ __launch_bounds__(128) void scan_kernel(const float* __restrict__ u,
                                                   const float* __restrict__ D) {
    __shared__ float su[SEQS][SPITCH];
    __shared__ float sy[SEQS][SPITCH];

    int tid  = threadIdx.x;
    int grp  = tid >> 3;
    int sub  = tid & 7;
    int gid0 = blockIdx.x * SEQS;
    int gid  = gid0 + grp;
    int h    = gid & (Hq - 1);
    float Dh = D[h];

    u64 wre2[4], nwim2[4], wim2[4], ccre2[4], nccim2[4], xre2[4], xim2[4];
    int base = h * Nq + sub * MPL;
#pragma unroll
    for (int p = 0; p < 4; p++) {
        float2 wr = *(const float2*)&g_wre[base + 2 * p];
        float2 wi = *(const float2*)&g_wim[base + 2 * p];
        float2 cr = *(const float2*)&g_cre[base + 2 * p];
        float2 ci = *(const float2*)&g_cim[base + 2 * p];
        wre2[p]   = pk2(wr.x, wr.y);
        wim2[p]   = pk2(wi.x, wi.y);
        nwim2[p]  = pk2(-wi.x, -wi.y);
        ccre2[p]  = pk2(cr.x, cr.y);
        nccim2[p] = pk2(-ci.x, -ci.y);
        xre2[p] = 0ull;
        xim2[p] = 0ull;
    }

    const float* ub = u + (size_t)gid0 * Lq;

    for (int c0 = 0; c0 < Lq; c0 += TCH) {
#pragma unroll
        for (int it = 0; it < (SEQS * TCH / 4) / 128; it++) {
            int idx = tid + it * 128;
            int r   = idx >> 6;
            int c4  = idx & 63;
            float4 v = *(const float4*)(ub + (size_t)r * Lq + c0 + c4 * 4);
            *(float4*)&su[r][c4 * 4] = v;
        }
        __syncthreads();

        for (int t0 = 0; t0 < TCH; t0 += 8) {
            float hold = 0.0f;
#pragma unroll
            for (int k = 0; k < 8; k++) {
                float us = su[grp][t0 + k];
                u64 u2   = pk2(us, us);
                u64 acc2a = 0ull, acc2b = 0ull;     // dual accumulators
#pragma unroll
                for (int p = 0; p < 4; p++) {
                    u64 t  = ffma2(nwim2[p], xim2[p], u2);
                    u64 nr = ffma2(wre2[p],  xre2[p], t);
                    u64 ni = fmul2(wim2[p],  xre2[p]);
                    ni     = ffma2(wre2[p],  xim2[p], ni);
                    xre2[p] = nr;
                    xim2[p] = ni;
                    if (p & 1) {
                        acc2b = ffma2(ccre2[p],  nr, acc2b);
                        acc2b = ffma2(nccim2[p], ni, acc2b);
                    } else {
                        acc2a = ffma2(ccre2[p],  nr, acc2a);
                        acc2a = ffma2(nccim2[p], ni, acc2a);
                    }
                }
                float2 aa = upk2(acc2a);
                float2 bb = upk2(acc2b);
                float v = (aa.x + aa.y) + (bb.x + bb.y);
                v += __shfl_xor_sync(0xFFFFFFFFu, v, 1);
                v += __shfl_xor_sync(0xFFFFFFFFu, v, 2);
                v += __shfl_xor_sync(0xFFFFFFFFu, v, 4);
                float y = fmaf(Dh, us, v);
                if (k == sub) hold = y;
            }
            float gel = 0.5f * hold * (1.0f + erff(hold * 0.70710678118654752f));
            sy[grp][t0 + sub] = gel;
        }
        __syncthreads();

#pragma unroll
        for (int it = 0; it < (SEQS * TCH / 4) / 128; it++) {
            int idx = tid + it * 128;
            int r   = idx >> 6;
            int c4  = idx & 63;
            float4 v = *(float4*)&sy[r][c4 * 4];
            __nv_bfloat16 h0 = __float2bfloat16(v.x);
            __nv_bfloat16 h1 = __float2bfloat16(v.y);
            __nv_bfloat16 h2 = __float2bfloat16(v.z);
            __nv_bfloat16 h3 = __float2bfloat16(v.w);
            __nv_bfloat16 l0b = __float2bfloat16(v.x - __bfloat162float(h0));
            __nv_bfloat16 l1b = __float2bfloat16(v.y - __bfloat162float(h1));
            __nv_bfloat16 l2b = __float2bfloat16(v.z - __bfloat162float(h2));
            __nv_bfloat16 l3b = __float2bfloat16(v.w - __bfloat162float(h3));
            uint2 ph, pl;
            ph.x = ((unsigned)__bfloat16_as_ushort(h1) << 16) | __bfloat16_as_ushort(h0);
            ph.y = ((unsigned)__bfloat16_as_ushort(h3) << 16) | __bfloat16_as_ushort(h2);
            pl.x = ((unsigned)__bfloat16_as_ushort(l1b) << 16) | __bfloat16_as_ushort(l0b);
            pl.y = ((unsigned)__bfloat16_as_ushort(l3b) << 16) | __bfloat16_as_ushort(l2b);
            size_t off = (size_t)(gid0 + r) * Lq + c0 + c4 * 4;
            *(uint2*)(g_yh + off) = ph;
            *(uint2*)(g_yl + off) = pl;
        }
        __syncthreads();
    }
}

// ---------------- kernel 3: bf16-split tensor-core GEMM, 2-stage pipeline --
// out[b] (512 x 2048) = W (512x512) @ Y[b] (512x2048) + bias
// 3-term split: Wh*Yh + Wl*Yh + Wh*Yl  (fp32 accumulate)
// MMA issue order: term-outermost so consecutive MMAs hit different
// accumulator fragments (dependency distance 16 >> mma latency).
#define GBM 128
#define GBN 128
#define GBK 32
#define ASTR 40    // As row stride (elems)
#define BSTR 136   // Bs row stride (elems)
#define A_ELEMS (GBM * ASTR)
#define B_ELEMS (GBK * BSTR)
#define AOFF(st, hl) (((st) * 2 + (hl)) * A_ELEMS * 2)
#define BOFF(st, hl) (4 * A_ELEMS * 2 + ((st) * 2 + (hl)) * B_ELEMS * 2)
#define SMEM_GEMM (4 * A_ELEMS * 2 + 4 * B_ELEMS * 2)

#define LDSM4(r0, r1, r2, r3, addr) \
    asm volatile("ldmatrix.sync.aligned.m8n8.x4.shared.b16 {%0,%1,%2,%3},[%4];" \
                 : "=r"(r0), "=r"(r1), "=r"(r2), "=r"(r3) : "r"(addr))
#define LDSM4T(r0, r1, r2, r3, addr) \
    asm volatile("ldmatrix.sync.aligned.m8n8.x4.trans.shared.b16 {%0,%1,%2,%3},[%4];" \
                 : "=r"(r0), "=r"(r1), "=r"(r2), "=r"(r3) : "r"(addr))
#define MMA16816(d, a, b0, b1) \
    asm volatile("mma.sync.aligned.m16n8k16.row.col.f32.bf16.bf16.f32 " \
                 "{%0,%1,%2,%3},{%4,%5,%6,%7},{%8,%9},{%0,%1,%2,%3};" \
                 : "+f"(d[0]), "+f"(d[1]), "+f"(d[2]), "+f"(d[3]) \
                 : "r"(a[0]), "r"(a[1]), "r"(a[2]), "r"(a[3]), "r"(b0), "r"(b1))
#define CPA16(dst, src) \
    asm volatile("cp.async.cg.shared.global [%0],[%1],16;" :: "r"(dst), "l"(src))

extern __shared__ char dsm[];

__device__ __forceinline__ unsigned smem_u32g(const void* p) {
    unsigned a;
    asm("{ .reg .u64 t; cvta.to.shared.u64 t, %1; cvt.u32.u64 %0, t; }"
        : "=r"(a) : "l"(p));
    return a;
}

__global__ __launch_bounds__(256) void gemm_kernel(const float* __restrict__ bias,
                                                   float* __restrict__ out) {
    unsigned sb = smem_u32g(dsm);
    int b   = blockIdx.z;
    int v0  = blockIdx.y * GBM;
    int l0  = blockIdx.x * GBN;
    int tid = threadIdx.x;
    int lane = tid & 31;
    int wid  = tid >> 5;
    int wm = wid >> 1;            // 0..3 -> m offset wm*32
    int wn = wid & 1;             // 0..1 -> n offset wn*64

    float acc[2][8][4];
#pragma unroll
    for (int i = 0; i < 2; i++)
#pragma unroll
        for (int j = 0; j < 8; j++)
#pragma unroll
            for (int k = 0; k < 4; k++) acc[i][j][k] = 0.0f;

#define LOAD_TILE(k0, st) do {                                              \
    _Pragma("unroll")                                                       \
    for (int q = 0; q < 2; q++) {                                           \
        int idx = tid + q * 256;                                            \
        int r = idx >> 2, c = (idx & 3) * 8;                                \
        size_t src = (size_t)(v0 + r) * Hq + (k0) + c;                      \
        unsigned d = (unsigned)(r * ASTR + c) * 2;                          \
        CPA16(sb + AOFF(st, 0) + d, g_Wh + src);                            \
        CPA16(sb + AOFF(st, 1) + d, g_Wl + src);                            \
    }                                                                       \
    _Pragma("unroll")                                                       \
    for (int q = 0; q < 2; q++) {                                           \
        int idx = tid + q * 256;                                            \
        int r = idx >> 4, c = (idx & 15) * 8;                               \
        size_t src = (size_t)(b * Hq + (k0) + r) * Lq + l0 + c;             \
        unsigned d = (unsigned)(r * BSTR + c) * 2;                          \
        CPA16(sb + BOFF(st, 0) + d, g_yh + src);                            \
        CPA16(sb + BOFF(st, 1) + d, g_yl + src);                            \
    }                                                                       \
} while (0)

    // prologue: stage tiles 0 and 1
    LOAD_TILE(0, 0);
    asm volatile("cp.async.commit_group;");
    LOAD_TILE(GBK, 1);
    asm volatile("cp.async.commit_group;");

    for (int ch = 0; ch < Hq / GBK; ch++) {
        int st = ch & 1;
        asm volatile("cp.async.wait_group 1;");
        __syncthreads();

        unsigned ah_base = sb + AOFF(st, 0);
        unsigned al_base = sb + AOFF(st, 1);
        unsigned bh_base = sb + BOFF(st, 0);
        unsigned bl_base = sb + BOFF(st, 1);

#pragma unroll
        for (int ks = 0; ks < 2; ks++) {
            unsigned ah[2][4], al[2][4], bh[4][4], bl[4][4];
#pragma unroll
            for (int mf = 0; mf < 2; mf++) {
                unsigned d = ((wm * 32 + mf * 16 + (lane & 15)) * ASTR
                              + ks * 16 + (lane >> 4) * 8) * 2;
                LDSM4(ah[mf][0], ah[mf][1], ah[mf][2], ah[mf][3], ah_base + d);
                LDSM4(al[mf][0], al[mf][1], al[mf][2], al[mf][3], al_base + d);
            }
#pragma unroll
            for (int j = 0; j < 4; j++) {
                unsigned d = ((ks * 16 + (lane & 15)) * BSTR
                              + wn * 64 + j * 16 + (lane >> 4) * 8) * 2;
                LDSM4T(bh[j][0], bh[j][1], bh[j][2], bh[j][3], bh_base + d);
                LDSM4T(bl[j][0], bl[j][1], bl[j][2], bl[j][3], bl_base + d);
            }
            // term 0: Wh x Yh  (16 independent accumulators back-to-back)
#pragma unroll
            for (int mf = 0; mf < 2; mf++)
#pragma unroll
                for (int n8 = 0; n8 < 8; n8++) {
                    int j = n8 >> 1, hi = (n8 & 1) * 2;
                    MMA16816(acc[mf][n8], ah[mf], bh[j][hi], bh[j][hi + 1]);
                }
            // term 1: Wl x Yh
#pragma unroll
            for (int mf = 0; mf < 2; mf++)
#pragma unroll
                for (int n8 = 0; n8 < 8; n8++) {
                    int j = n8 >> 1, hi = (n8 & 1) * 2;
                    MMA16816(acc[mf][n8], al[mf], bh[j][hi], bh[j][hi + 1]);
                }
            // term 2: Wh x Yl
#pragma unroll
            for (int mf = 0; mf < 2; mf++)
#pragma unroll
                for (int n8 = 0; n8 < 8; n8++) {
                    int j = n8 >> 1, hi = (n8 & 1) * 2;
                    MMA16816(acc[mf][n8], ah[mf], bl[j][hi], bl[j][hi + 1]);
                }
        }
        __syncthreads();

        int knext = (ch + 2) * GBK;
        if (knext < Hq) {
            LOAD_TILE(knext, st);
        }
        asm volatile("cp.async.commit_group;");
    }

    // ---- epilogue: bias + store ----
    int tq = lane >> 2, tr = lane & 3;
#pragma unroll
    for (int mf = 0; mf < 2; mf++) {
        int v = v0 + wm * 32 + mf * 16 + tq;
        float bv0 = bias[v], bv1 = bias[v + 8];
#pragma unroll
        for (int n8 = 0; n8 < 8; n8++) {
            int l = l0 + wn * 64 + n8 * 8 + tr * 2;
            float2 s0, s1;
            s0.x = acc[mf][n8][0] + bv0; s0.y = acc[mf][n8][1] + bv0;
            s1.x = acc[mf][n8][2] + bv1; s1.y = acc[mf][n8][3] + bv1;
            *(float2*)(out + ((size_t)b * Hq + v) * Lq + l)     = s0;
            *(float2*)(out + ((size_t)b * Hq + v + 8) * Lq + l) = s1;
        }
    }
}

// ---------------- launch ----------------------------------------------------
extern "C" void kernel_launch(void* const* d_in, const int* in_sizes, int n_in,
                              void* d_out, int out_size) {
    (void)in_sizes; (void)n_in; (void)out_size;
    const float* u      = (const float*)d_in[0];
    const float* log_dt = (const float*)d_in[1];
    const float* A_re   = (const float*)d_in[2];
    const float* A_im   = (const float*)d_in[3];
    const float* C_re   = (const float*)d_in[4];
    const float* C_im   = (const float*)d_in[5];
    const float* D      = (const float*)d_in[6];
    const float* W      = (const float*)d_in[7];
    const float* bias   = (const float*)d_in[8];
    float* out = (float*)d_out;

    static int smem_set = 0;
    if (!smem_set) {
        cudaFuncSetAttribute(gemm_kernel,
                             cudaFuncAttributeMaxDynamicSharedMemorySize,
                             SMEM_GEMM);
        smem_set = 1;
    }

    prep_kernel<<<(Hq * Hq + 255) / 256, 256>>>(log_dt, A_re, A_im, C_re, C_im, W);
    scan_kernel<<<Bq * Hq / SEQS, 128>>>(u, D);
    dim3 g(Lq / GBN, Hq / GBM, Bq);
    gemm_kernel<<<g, 256, SMEM_GEMM>>>(bias, out);
}

// round 8
// speedup vs baseline: 1.6619x; 1.1121x over previous
#include <cuda_runtime.h>
#include <cuda_bf16.h>
#include <cuda_fp16.h>
#include <math.h>

#define Bq 16
#define Hq 512
#define Nq 64
#define Lq 2048

// ---------------- scratch (device globals: no allocation allowed) ----------
__device__ __half g_yf[Bq * Hq * Lq];                // activations fp16 (32 MB)
__device__ __half g_Wh[Hq * Hq], g_Wl[Hq * Hq];      // W exact fp16 split
__device__ float g_wre[Hq * Nq], g_wim[Hq * Nq];
__device__ float g_cre[Hq * Nq], g_cim[Hq * Nq];

// ---------------- f32x2 packed-math helpers --------------------------------
typedef unsigned long long u64;
__device__ __forceinline__ u64 pk2(float a, float b) {
    u64 r; asm("mov.b64 %0,{%1,%2};" : "=l"(r) : "f"(a), "f"(b)); return r;
}
__device__ __forceinline__ float2 upk2(u64 v) {
    float2 f; asm("mov.b64 {%0,%1},%2;" : "=f"(f.x), "=f"(f.y) : "l"(v)); return f;
}
__device__ __forceinline__ u64 ffma2(u64 a, u64 b, u64 c) {
    u64 d; asm("fma.rn.f32x2 %0,%1,%2,%3;" : "=l"(d) : "l"(a), "l"(b), "l"(c)); return d;
}
__device__ __forceinline__ u64 fmul2(u64 a, u64 b) {
    u64 d; asm("mul.rn.f32x2 %0,%1,%2;" : "=l"(d) : "l"(a), "l"(b)); return d;
}

// ---------------- kernel 1: params + W fp16 split (fused) ------------------
__global__ void prep_kernel(const float* __restrict__ log_dt,
                            const float* __restrict__ A_re,
                            const float* __restrict__ A_im,
                            const float* __restrict__ C_re,
                            const float* __restrict__ C_im,
                            const float* __restrict__ W) {
    int i = blockIdx.x * blockDim.x + threadIdx.x;
    if (i < Hq * Hq) {
        float w = W[i];
        __half h = __float2half_rn(w);
        g_Wh[i] = h;
        g_Wl[i] = __float2half_rn(w - __half2float(h));
    }
    if (i < Hq * Nq) {
        int h = i / Nq;
        float dt  = expf(log_dt[h]);
        float ar  = -expf(A_re[i]);       // Re(A) < 0
        float ai  = A_im[i];
        float er  = expf(dt * ar);
        float wre = er * cosf(dt * ai);
        float wim = er * sinf(dt * ai);
        float den  = ar * ar + ai * ai;   // (w-1)/A via conjugate
        float numr = wre - 1.0f, numi = wim;
        float qre  = (numr * ar + numi * ai) / den;
        float qim  = (numi * ar - numr * ai) / den;
        float cr = C_re[i], ci = C_im[i];
        g_wre[i] = wre;
        g_wim[i] = wim;
        g_cre[i] = 2.0f * (cr * qre - ci * qim);
        g_cim[i] = 2.0f * (cr * qim + ci * qre);
    }
}

// ---------------- kernel 2: diagonal SSM scan (f32x2) + skip + GELU --------
#define MPL   8
#define SEQS  16
#define TCH   256
#define SPITCH 260

__global__ __launch_bounds__(128) void scan_kernel(const float* __restrict__ u,
                                                   const float* __restrict__ D) {
    __shared__ float su[SEQS][SPITCH];
    __shared__ float sy[SEQS][SPITCH];

    int tid  = threadIdx.x;
    int grp  = tid >> 3;
    int sub  = tid & 7;
    int gid0 = blockIdx.x * SEQS;
    int gid  = gid0 + grp;
    int h    = gid & (Hq - 1);
    float Dh = D[h];

    u64 wre2[4], nwim2[4], wim2[4], ccre2[4], nccim2[4], xre2[4], xim2[4];
    int base = h * Nq + sub * MPL;
#pragma unroll
    for (int p = 0; p < 4; p++) {
        float2 wr = *(const float2*)&g_wre[base + 2 * p];
        float2 wi = *(const float2*)&g_wim[base + 2 * p];
        float2 cr = *(const float2*)&g_cre[base + 2 * p];
        float2 ci = *(const float2*)&g_cim[base + 2 * p];
        wre2[p]   = pk2(wr.x, wr.y);
        wim2[p]   = pk2(wi.x, wi.y);
        nwim2[p]  = pk2(-wi.x, -wi.y);
        ccre2[p]  = pk2(cr.x, cr.y);
        nccim2[p] = pk2(-ci.x, -ci.y);
        xre2[p] = 0ull;
        xim2[p] = 0ull;
    }

    const float* ub = u + (size_t)gid0 * Lq;

    for (int c0 = 0; c0 < Lq; c0 += TCH) {
#pragma unroll
        for (int it = 0; it < (SEQS * TCH / 4) / 128; it++) {
            int idx = tid + it * 128;
            int r   = idx >> 6;
            int c4  = idx & 63;
            float4 v = *(const float4*)(ub + (size_t)r * Lq + c0 + c4 * 4);
            *(float4*)&su[r][c4 * 4] = v;
        }
        __syncthreads();

        for (int t0 = 0; t0 < TCH; t0 += 8) {
            float hold = 0.0f;
#pragma unroll
            for (int k = 0; k < 8; k++) {
                float us = su[grp][t0 + k];
                u64 u2   = pk2(us, us);
                u64 acc2a = 0ull, acc2b = 0ull;
#pragma unroll
                for (int p = 0; p < 4; p++) {
                    u64 t  = ffma2(nwim2[p], xim2[p], u2);
                    u64 nr = ffma2(wre2[p],  xre2[p], t);
                    u64 ni = fmul2(wim2[p],  xre2[p]);
                    ni     = ffma2(wre2[p],  xim2[p], ni);
                    xre2[p] = nr;
                    xim2[p] = ni;
                    if (p & 1) {
                        acc2b = ffma2(ccre2[p],  nr, acc2b);
                        acc2b = ffma2(nccim2[p], ni, acc2b);
                    } else {
                        acc2a = ffma2(ccre2[p],  nr, acc2a);
                        acc2a = ffma2(nccim2[p], ni, acc2a);
                    }
                }
                float2 aa = upk2(acc2a);
                float2 bb = upk2(acc2b);
                float v = (aa.x + aa.y) + (bb.x + bb.y);
                v += __shfl_xor_sync(0xFFFFFFFFu, v, 1);
                v += __shfl_xor_sync(0xFFFFFFFFu, v, 2);
                v += __shfl_xor_sync(0xFFFFFFFFu, v, 4);
                float y = fmaf(Dh, us, v);
                if (k == sub) hold = y;
            }
            float gel = 0.5f * hold * (1.0f + erff(hold * 0.70710678118654752f));
            sy[grp][t0 + sub] = gel;
        }
        __syncthreads();

        // store activations as fp16
#pragma unroll
        for (int it = 0; it < (SEQS * TCH / 4) / 128; it++) {
            int idx = tid + it * 128;
            int r   = idx >> 6;
            int c4  = idx & 63;
            float4 v = *(float4*)&sy[r][c4 * 4];
            __half2 p0 = __floats2half2_rn(v.x, v.y);
            __half2 p1 = __floats2half2_rn(v.z, v.w);
            uint2 pk;
            pk.x = *(unsigned*)&p0;
            pk.y = *(unsigned*)&p1;
            size_t off = (size_t)(gid0 + r) * Lq + c0 + c4 * 4;
            *(uint2*)(g_yf + off) = pk;
        }
        __syncthreads();
    }
}

// ---------------- kernel 3: fp16 2-term tensor-core GEMM, 2-stage pipeline -
// out[b] (512 x 2048) = W (512x512) @ Y[b] (512x2048) + bias
// W = Wh + Wl (exact fp16 split), Y single fp16:
//   out = Wh*Y + Wl*Y   (fp32 accumulate; error ~ fp16 quant of Y ~1e-4)
#define GBM 128
#define GBN 128
#define GBK 32
#define ASTR 40    // As row stride (elems)
#define BSTR 136   // Bs row stride (elems)
#define A_ELEMS (GBM * ASTR)
#define B_ELEMS (GBK * BSTR)
#define AOFF(st, hl) (((st) * 2 + (hl)) * A_ELEMS * 2)
#define BOFF(st) (4 * A_ELEMS * 2 + (st) * B_ELEMS * 2)
#define SMEM_GEMM (4 * A_ELEMS * 2 + 2 * B_ELEMS * 2)

#define LDSM4(r0, r1, r2, r3, addr) \
    asm volatile("ldmatrix.sync.aligned.m8n8.x4.shared.b16 {%0,%1,%2,%3},[%4];" \
                 : "=r"(r0), "=r"(r1), "=r"(r2), "=r"(r3) : "r"(addr))
#define LDSM4T(r0, r1, r2, r3, addr) \
    asm volatile("ldmatrix.sync.aligned.m8n8.x4.trans.shared.b16 {%0,%1,%2,%3},[%4];" \
                 : "=r"(r0), "=r"(r1), "=r"(r2), "=r"(r3) : "r"(addr))
#define MMA16816(d, a, b0, b1) \
    asm volatile("mma.sync.aligned.m16n8k16.row.col.f32.f16.f16.f32 " \
                 "{%0,%1,%2,%3},{%4,%5,%6,%7},{%8,%9},{%0,%1,%2,%3};" \
                 : "+f"(d[0]), "+f"(d[1]), "+f"(d[2]), "+f"(d[3]) \
                 : "r"(a[0]), "r"(a[1]), "r"(a[2]), "r"(a[3]), "r"(b0), "r"(b1))
#define CPA16(dst, src) \
    asm volatile("cp.async.cg.shared.global [%0],[%1],16;" :: "r"(dst), "l"(src))

extern __shared__ char dsm[];

__device__ __forceinline__ unsigned smem_u32g(const void* p) {
    unsigned a;
    asm("{ .reg .u64 t; cvta.to.shared.u64 t, %1; cvt.u32.u64 %0, t; }"
        : "=r"(a) : "l"(p));
    return a;
}

__global__ __launch_bounds__(256) void gemm_kernel(const float* __restrict__ bias,
                                                   float* __restrict__ out) {
    unsigned sb = smem_u32g(dsm);
    int b   = blockIdx.z;
    int v0  = blockIdx.y * GBM;
    int l0  = blockIdx.x * GBN;
    int tid = threadIdx.x;
    int lane = tid & 31;
    int wid  = tid >> 5;
    int wm = wid >> 1;            // 0..3 -> m offset wm*32
    int wn = wid & 1;             // 0..1 -> n offset wn*64

    float acc[2][8][4];
#pragma unroll
    for (int i = 0; i < 2; i++)
#pragma unroll
        for (int j = 0; j < 8; j++)
#pragma unroll
            for (int k = 0; k < 4; k++) acc[i][j][k] = 0.0f;

#define LOAD_TILE(k0, st) do {                                              \
    _Pragma("unroll")                                                       \
    for (int q = 0; q < 2; q++) {                                           \
        int idx = tid + q * 256;                                            \
        int r = idx >> 2, c = (idx & 3) * 8;                                \
        size_t src = (size_t)(v0 + r) * Hq + (k0) + c;                      \
        unsigned d = (unsigned)(r * ASTR + c) * 2;                          \
        CPA16(sb + AOFF(st, 0) + d, g_Wh + src);                            \
        CPA16(sb + AOFF(st, 1) + d, g_Wl + src);                            \
    }                                                                       \
    _Pragma("unroll")                                                       \
    for (int q = 0; q < 2; q++) {                                           \
        int idx = tid + q * 256;                                            \
        int r = idx >> 4, c = (idx & 15) * 8;                               \
        size_t src = (size_t)(b * Hq + (k0) + r) * Lq + l0 + c;             \
        unsigned d = (unsigned)(r * BSTR + c) * 2;                          \
        CPA16(sb + BOFF(st) + d, g_yf + src);                               \
    }                                                                       \
} while (0)

    // prologue: stage tiles 0 and 1
    LOAD_TILE(0, 0);
    asm volatile("cp.async.commit_group;");
    LOAD_TILE(GBK, 1);
    asm volatile("cp.async.commit_group;");

    for (int ch = 0; ch < Hq / GBK; ch++) {
        int st = ch & 1;
        asm volatile("cp.async.wait_group 1;");
        __syncthreads();

        unsigned ah_base = sb + AOFF(st, 0);
        unsigned al_base = sb + AOFF(st, 1);
        unsigned bh_base = sb + BOFF(st);

#pragma unroll
        for (int ks = 0; ks < 2; ks++) {
            unsigned ah[2][4], al[2][4], bh[4][4];
#pragma unroll
            for (int mf = 0; mf < 2; mf++) {
                unsigned d = ((wm * 32 + mf * 16 + (lane & 15)) * ASTR
                              + ks * 16 + (lane >> 4) * 8) * 2;
                LDSM4(ah[mf][0], ah[mf][1], ah[mf][2], ah[mf][3], ah_base + d);
                LDSM4(al[mf][0], al[mf][1], al[mf][2], al[mf][3], al_base + d);
            }
#pragma unroll
            for (int j = 0; j < 4; j++) {
                unsigned d = ((ks * 16 + (lane & 15)) * BSTR
                              + wn * 64 + j * 16 + (lane >> 4) * 8) * 2;
                LDSM4T(bh[j][0], bh[j][1], bh[j][2], bh[j][3], bh_base + d);
            }
            // term 0: Wh x Y
#pragma unroll
            for (int mf = 0; mf < 2; mf++)
#pragma unroll
                for (int n8 = 0; n8 < 8; n8++) {
                    int j = n8 >> 1, hi = (n8 & 1) * 2;
                    MMA16816(acc[mf][n8], ah[mf], bh[j][hi], bh[j][hi + 1]);
                }
            // term 1: Wl x Y
#pragma unroll
            for (int mf = 0; mf < 2; mf++)
#pragma unroll
                for (int n8 = 0; n8 < 8; n8++) {
                    int j = n8 >> 1, hi = (n8 & 1) * 2;
                    MMA16816(acc[mf][n8], al[mf], bh[j][hi], bh[j][hi + 1]);
                }
        }
        __syncthreads();

        int knext = (ch + 2) * GBK;
        if (knext < Hq) {
            LOAD_TILE(knext, st);
        }
        asm volatile("cp.async.commit_group;");
    }

    // ---- epilogue: bias + store ----
    int tq = lane >> 2, tr = lane & 3;
#pragma unroll
    for (int mf = 0; mf < 2; mf++) {
        int v = v0 + wm * 32 + mf * 16 + tq;
        float bv0 = bias[v], bv1 = bias[v + 8];
#pragma unroll
        for (int n8 = 0; n8 < 8; n8++) {
            int l = l0 + wn * 64 + n8 * 8 + tr * 2;
            float2 s0, s1;
            s0.x = acc[mf][n8][0] + bv0; s0.y = acc[mf][n8][1] + bv0;
            s1.x = acc[mf][n8][2] + bv1; s1.y = acc[mf][n8][3] + bv1;
            *(float2*)(out + ((size_t)b * Hq + v) * Lq + l)     = s0;
            *(float2*)(out + ((size_t)b * Hq + v + 8) * Lq + l) = s1;
        }
    }
}

// ---------------- launch ----------------------------------------------------
extern "C" void kernel_launch(void* const* d_in, const int* in_sizes, int n_in,
                              void* d_out, int out_size) {
    (void)in_sizes; (void)n_in; (void)out_size;
    const float* u      = (const float*)d_in[0];
    const float* log_dt = (const float*)d_in[1];
    const float* A_re   = (const float*)d_in[2];
    const float* A_im   = (const float*)d_in[3];
    const float* C_re   = (const float*)d_in[4];
    const float* C_im   = (const float*)d_in[5];
    const float* D      = (const float*)d_in[6];
    const float* W      = (const float*)d_in[7];
    const float* bias   = (const float*)d_in[8];
    float* out = (float*)d_out;

    static int smem_set = 0;
    if (!smem_set) {
        cudaFuncSetAttribute(gemm_kernel,
                             cudaFuncAttributeMaxDynamicSharedMemorySize,
                             SMEM_GEMM);
        smem_set = 1;
    }

    prep_kernel<<<(Hq * Hq + 255) / 256, 256>>>(log_dt, A_re, A_im, C_re, C_im, W);
    scan_kernel<<<Bq * Hq / SEQS, 128>>>(u, D);
    dim3 g(Lq / GBN, Hq / GBM, Bq);
    gemm_kernel<<<g, 256, SMEM_GEMM>>>(bias, out);
}